// round 1
// baseline (speedup 1.0000x reference)
#include <cuda_runtime.h>
#include <math.h>

#define NB 4096
#define NF 256
#define NP 5000
#define TK 32
#define TP 128
#define KC 64
#define NBLK (NB / TK)            // 128 CTAs
#define BSTR (TP + 4)             // 132: pad keeps LDS.128 conflict-free & 16B-aligned
#define CAP 64
#define OIM_SCALAR_F 30.0f
#define IGNORE_INDEX 5554
#define NTILES ((NP + TP - 1) / TP)   // 40

// Scratch (no allocations allowed in kernel_launch)
__device__ float g_partials[NBLK][3];   // fc, inst, ce per CTA
__device__ float g_n[3];                // n1, n2, n3

// ---------------------------------------------------------------------------
// K0: normalizer counts
// ---------------------------------------------------------------------------
__global__ void prep_kernel(const int* __restrict__ roi_label,
                            const int* __restrict__ reid_labels) {
    __shared__ int cnt[3];
    int tid = threadIdx.x;
    if (tid < 3) cnt[tid] = 0;
    __syncthreads();
    int c1 = 0, c2 = 0, c3 = 0;
    for (int k = tid; k < NB; k += blockDim.x) {
        int t = roi_label[k] - 1;
        bool v = (t >= 0);
        int label = v ? t : 0;
        int lreid = reid_labels[label];
        bool v2 = v && (lreid >= 0);
        int lr = lreid > 0 ? lreid : 0;
        bool v3 = v2 && (lr != IGNORE_INDEX);
        c1 += v ? 1 : 0;
        c2 += v2 ? 1 : 0;
        c3 += v3 ? 1 : 0;
    }
    atomicAdd(&cnt[0], c1);
    atomicAdd(&cnt[1], c2);
    atomicAdd(&cnt[2], c3);
    __syncthreads();
    if (tid < 3) g_n[tid] = fmaxf((float)cnt[tid], 1.0f);
}

// ---------------------------------------------------------------------------
// Fused GEMM + loss pass. MODE 0 = instance loss, MODE 1 = reid CE.
// Per-warp: 4 consecutive k-rows. Per-lane: 4 consecutive p-cols of a 128-tile.
// ---------------------------------------------------------------------------
template <int MODE>
__device__ __forceinline__ float gemm_pass(
    const float* __restrict__ lut,
    const int* __restrict__ reid_labels,
    const float* __restrict__ As,   // [TK][NF]
    float* __restrict__ Bs,         // [KC][BSTR]
    float* __restrict__ pos_x,      // [TK][CAP]
    int* __restrict__ pos_cnt,      // [TK]
    const int* __restrict__ s_lreid,
    const float* __restrict__ s_w2,
    const int* __restrict__ s_lr,
    const float* __restrict__ s_w3,
    int warp, int lane, int tid)
{
    float m[4], s[4], xt[4];
    int lre[4], lrr[4];
    float w2r[4];
#pragma unroll
    for (int i = 0; i < 4; i++) {
        m[i] = -1e30f; s[i] = 0.0f; xt[i] = -1e30f;
        int k = warp * 4 + i;
        lre[i] = s_lreid[k];
        w2r[i] = s_w2[k];
        lrr[i] = s_lr[k];
    }

    for (int pt = 0; pt < NTILES; pt++) {
        int p0 = pt * TP;
        float acc[4][4];
#pragma unroll
        for (int i = 0; i < 4; i++)
#pragma unroll
            for (int j = 0; j < 4; j++) acc[i][j] = 0.0f;

#pragma unroll
        for (int c = 0; c < NF / KC; c++) {
            int f0 = c * KC;
            __syncthreads();
            // stage B tile transposed: Bs[f][p], coalesced global reads
#pragma unroll
            for (int it = 0; it < (TP * KC) / 256; it++) {
                int idx = it * 256 + tid;
                int ff = idx & (KC - 1);
                int pp = idx >> 6;
                int p = p0 + pp;
                Bs[ff * BSTR + pp] = (p < NP) ? __ldg(&lut[(size_t)p * NF + f0 + ff]) : 0.0f;
            }
            __syncthreads();
#pragma unroll
            for (int f = 0; f < KC; f += 4) {
                float4 b0 = *(const float4*)&Bs[(f + 0) * BSTR + lane * 4];
                float4 b1 = *(const float4*)&Bs[(f + 1) * BSTR + lane * 4];
                float4 b2 = *(const float4*)&Bs[(f + 2) * BSTR + lane * 4];
                float4 b3 = *(const float4*)&Bs[(f + 3) * BSTR + lane * 4];
#pragma unroll
                for (int i = 0; i < 4; i++) {
                    float4 av = *(const float4*)&As[(warp * 4 + i) * NF + f0 + f];
                    acc[i][0] += av.x * b0.x + av.y * b1.x + av.z * b2.x + av.w * b3.x;
                    acc[i][1] += av.x * b0.y + av.y * b1.y + av.z * b2.y + av.w * b3.y;
                    acc[i][2] += av.x * b0.z + av.y * b1.z + av.z * b2.z + av.w * b3.z;
                    acc[i][3] += av.x * b0.w + av.y * b1.w + av.z * b2.w + av.w * b3.w;
                }
            }
        }

        // epilogue: online logsumexp, positive collection / target capture
#pragma unroll
        for (int j = 0; j < 4; j++) {
            int p = p0 + lane * 4 + j;
            if (p >= NP) continue;
            int rl = (MODE == 0) ? reid_labels[p] : 0;
#pragma unroll
            for (int i = 0; i < 4; i++) {
                float x = acc[i][j] * OIM_SCALAR_F;
                if (MODE == 0) {
                    if (rl == lre[i]) {
                        if (w2r[i] > 0.0f) {
                            int k = warp * 4 + i;
                            int idx = atomicAdd(&pos_cnt[k], 1);
                            if (idx < CAP) pos_x[k * CAP + idx] = x;
                        }
                    } else {
                        if (x > m[i]) { s[i] = s[i] * __expf(m[i] - x) + 1.0f; m[i] = x; }
                        else          { s[i] += __expf(x - m[i]); }
                    }
                } else {
                    if (x > m[i]) { s[i] = s[i] * __expf(m[i] - x) + 1.0f; m[i] = x; }
                    else          { s[i] += __expf(x - m[i]); }
                    if (p == lrr[i]) xt[i] = x;
                }
            }
        }
    }

    // warp-level (m,s) combine; all lanes end with the full reduction
#pragma unroll
    for (int i = 0; i < 4; i++) {
#pragma unroll
        for (int o = 16; o; o >>= 1) {
            float mo = __shfl_xor_sync(0xffffffffu, m[i], o);
            float so = __shfl_xor_sync(0xffffffffu, s[i], o);
            float M = fmaxf(m[i], mo);
            s[i] = s[i] * __expf(m[i] - M) + so * __expf(mo - M);
            m[i] = M;
            if (MODE == 1) {
                float xo = __shfl_xor_sync(0xffffffffu, xt[i], o);
                xt[i] = fmaxf(xt[i], xo);
            }
        }
    }
    __syncwarp();

    float res = 0.0f;
#pragma unroll
    for (int i = 0; i < 4; i++) {
        if (lane == i) {   // lane i finalizes row warp*4+i (compile-time reg index)
            int k = warp * 4 + i;
            float lse = (s[i] > 0.0f) ? (m[i] + logf(s[i])) : -1e30f;
            if (MODE == 0) {
                if (w2r[i] > 0.0f) {
                    int c = pos_cnt[k];
                    int cl = c < CAP ? c : CAP;
                    float sum = 0.0f;
                    for (int q = 0; q < cl; q++)
                        sum += log1pf(expf(lse - pos_x[k * CAP + q]));
                    res = sum / fmaxf((float)c, 1.0f);
                }
            } else {
                res = (lse - xt[i]) * s_w3[k];
            }
        }
    }
    return res;
}

// ---------------------------------------------------------------------------
// K1: main fused kernel (one CTA = 32 rows, loops over all 5000 LUT rows x2)
// ---------------------------------------------------------------------------
__global__ void __launch_bounds__(256)
main_kernel(const float* __restrict__ inputs,
            const int* __restrict__ roi_label,
            const float* __restrict__ lut_inst,
            const float* __restrict__ reid_lut,
            const int* __restrict__ reid_labels)
{
    extern __shared__ float sm[];
    float* As    = sm;                        // TK*NF
    float* Bs    = As + TK * NF;              // KC*BSTR
    float* pos_x = Bs + KC * BSTR;            // TK*CAP
    int* pos_cnt = (int*)(pos_x + TK * CAP);  // TK
    int* s_label = pos_cnt + TK;
    int* s_lreid = s_label + TK;
    int* s_lr    = s_lreid + TK;
    float* s_w1  = (float*)(s_lr + TK);
    float* s_w2  = s_w1 + TK;
    float* s_w3  = s_w2 + TK;
    float* s_red = s_w3 + TK;                 // 8 warps * 3

    int tid = threadIdx.x;
    int warp = tid >> 5, lane = tid & 31;
    int r0 = blockIdx.x * TK;

    // stage A tile
    {
        const float4* gin = (const float4*)(inputs + (size_t)r0 * NF);
        float4* As4 = (float4*)As;
#pragma unroll
        for (int i = 0; i < (TK * NF / 4) / 256; i++)
            As4[tid + i * 256] = gin[tid + i * 256];
    }
    // per-row metadata
    if (tid < TK) {
        int t = roi_label[r0 + tid] - 1;
        bool v = (t >= 0);
        int label = v ? t : 0;
        int lreid = reid_labels[label];
        bool v2 = v && (lreid >= 0);
        int lr = lreid > 0 ? lreid : 0;
        bool v3 = v2 && (lr != IGNORE_INDEX);
        s_label[tid] = label;
        s_lreid[tid] = lreid;
        s_lr[tid] = lr;
        s_w1[tid] = v ? 1.0f : 0.0f;
        s_w2[tid] = v2 ? 1.0f : 0.0f;
        s_w3[tid] = v3 ? 1.0f : 0.0f;
        pos_cnt[tid] = 0;
    }
    __syncthreads();

    // feature consistency (MSE over valid rows)
    float fc = 0.0f;
#pragma unroll
    for (int i = 0; i < 4; i++) {
        int k = warp * 4 + i;
        if (s_w1[k] > 0.0f) {
            const float* lrow = lut_inst + (size_t)s_label[k] * NF;
            float a = 0.0f;
            for (int f = lane; f < NF; f += 32) {
                float d = lrow[f] - As[k * NF + f];
                a += d * d;
            }
#pragma unroll
            for (int o = 16; o; o >>= 1) a += __shfl_xor_sync(0xffffffffu, a, o);
            fc += a;   // identical on all lanes; only lane 0 is recorded below
        }
    }

    float inst = gemm_pass<0>(lut_inst, reid_labels, As, Bs, pos_x, pos_cnt,
                              s_lreid, s_w2, s_lr, s_w3, warp, lane, tid);
    float ce   = gemm_pass<1>(reid_lut, reid_labels, As, Bs, pos_x, pos_cnt,
                              s_lreid, s_w2, s_lr, s_w3, warp, lane, tid);

    // deterministic per-CTA reduction (no float atomics)
#pragma unroll
    for (int o = 16; o; o >>= 1) {
        inst += __shfl_xor_sync(0xffffffffu, inst, o);
        ce   += __shfl_xor_sync(0xffffffffu, ce, o);
    }
    if (lane == 0) {
        s_red[warp * 3 + 0] = fc;
        s_red[warp * 3 + 1] = inst;
        s_red[warp * 3 + 2] = ce;
    }
    __syncthreads();
    if (tid == 0) {
        float a = 0.0f, b = 0.0f, c = 0.0f;
        for (int w = 0; w < 8; w++) {
            a += s_red[w * 3 + 0];
            b += s_red[w * 3 + 1];
            c += s_red[w * 3 + 2];
        }
        g_partials[blockIdx.x][0] = a;
        g_partials[blockIdx.x][1] = b;
        g_partials[blockIdx.x][2] = c;
    }
}

// ---------------------------------------------------------------------------
// K2: finalize
// ---------------------------------------------------------------------------
__global__ void finalize_kernel(float* __restrict__ out) {
    float a = 0.0f, b = 0.0f, c = 0.0f;
    for (int i = threadIdx.x; i < NBLK; i += 32) {
        a += g_partials[i][0];
        b += g_partials[i][1];
        c += g_partials[i][2];
    }
#pragma unroll
    for (int o = 16; o; o >>= 1) {
        a += __shfl_xor_sync(0xffffffffu, a, o);
        b += __shfl_xor_sync(0xffffffffu, b, o);
        c += __shfl_xor_sync(0xffffffffu, c, o);
    }
    if (threadIdx.x == 0)
        out[0] = a / (g_n[0] * (float)NF) + c / g_n[2] + b / g_n[1];
}

// ---------------------------------------------------------------------------
extern "C" void kernel_launch(void* const* d_in, const int* in_sizes, int n_in,
                              void* d_out, int out_size) {
    const float* inputs      = (const float*)d_in[0];
    const int*   roi_label   = (const int*)d_in[1];
    const float* lut_inst    = (const float*)d_in[2];
    const float* reid_lut    = (const float*)d_in[3];
    const int*   reid_labels = (const int*)d_in[4];
    float* out = (float*)d_out;

    size_t smem_bytes = (size_t)(TK * NF + KC * BSTR + TK * CAP) * 4
                      + (size_t)(TK * 4) * 4      // pos_cnt + label + lreid + lr
                      + (size_t)(TK * 3) * 4      // w1,w2,w3
                      + (size_t)(8 * 3) * 4;      // s_red
    cudaFuncSetAttribute(main_kernel, cudaFuncAttributeMaxDynamicSharedMemorySize,
                         (int)smem_bytes);

    prep_kernel<<<1, 256>>>(roi_label, reid_labels);
    main_kernel<<<NBLK, 256, smem_bytes>>>(inputs, roi_label, lut_inst, reid_lut,
                                           reid_labels);
    finalize_kernel<<<1, 32>>>(out);
}

// round 3
// speedup vs baseline: 2.6332x; 2.6332x over previous
#include <cuda_runtime.h>
#include <math.h>
#include <stdint.h>

#define NB 4096
#define NF 256
#define NP 5000
#define NCHUNK 5
#define CHUNK_P 1024
#define TILE_M 128
#define NMTILE 32
#define CAPC 16
#define IGNORE_INDEX 5554
#define AS 260              // A smem row stride (floats): 260%32=4 -> conflict-free frags
#define BS 36               // B smem row stride (floats): 36%32=4 -> conflict-free frags
#define A_BYTES (TILE_M * AS * 4)          // 133120
#define B_STAGE_BYTES (256 * BS * 4)       // 36864
#define SM_META_OFF (A_BYTES + 2 * B_STAGE_BYTES)   // 206848
#define SMEM_TOTAL (SM_META_OFF + 4 * 128 * 4)      // 208896

// ---------------- global scratch ----------------
__device__ float g_s_inst[NB * NCHUNK * 4];
__device__ float g_s_reid[NB * NCHUNK * 4];
__device__ int   g_pcnt[NB * NCHUNK];
__device__ float g_posx[NB * NCHUNK * CAPC];
__device__ int   g_posp[NB * NCHUNK * CAPC];
__device__ float g_xt[NB];
__device__ float g_fc[NMTILE];
__device__ float g_part[NMTILE][5];

// ---------------- helpers ----------------
__device__ __forceinline__ uint32_t smem_u32(const void* p) {
    uint32_t a;
    asm("{ .reg .u64 t; cvta.to.shared.u64 t, %1; cvt.u32.u64 %0, t; }"
        : "=r"(a) : "l"(p));
    return a;
}

__device__ __forceinline__ void cp16(uint32_t dst, const void* src, int sz) {
    asm volatile("cp.async.cg.shared.global [%0], [%1], 16, %2;"
                 :: "r"(dst), "l"(src), "r"(sz) : "memory");
}
#define CP_COMMIT()  asm volatile("cp.async.commit_group;" ::: "memory")
#define CP_WAIT1()   asm volatile("cp.async.wait_group 1;" ::: "memory")

__device__ __forceinline__ void mma8(float* c, const uint32_t* a,
                                     uint32_t b0, uint32_t b1) {
    asm("mma.sync.aligned.m16n8k8.row.col.f32.tf32.tf32.f32 "
        "{%0,%1,%2,%3}, {%4,%5,%6,%7}, {%8,%9}, {%0,%1,%2,%3};"
        : "+f"(c[0]), "+f"(c[1]), "+f"(c[2]), "+f"(c[3])
        : "r"(a[0]), "r"(a[1]), "r"(a[2]), "r"(a[3]), "r"(b0), "r"(b1));
}

// ---------------------------------------------------------------------------
// Main fused kernel: grid (32 m-tiles, 5 p-chunks), 256 threads.
// Warp grid 2(m)x4(n); warp tile 64x64; ntiles: 0-3 instance LUT, 4-7 reid LUT.
// ---------------------------------------------------------------------------
__global__ void __launch_bounds__(256, 1)
main_kernel(const float* __restrict__ inputs,
            const int* __restrict__ roi_label,
            const float* __restrict__ lut_inst,
            const float* __restrict__ reid_lut,
            const int* __restrict__ reid_labels)
{
    extern __shared__ char smem[];
    float* sA = (float*)smem;
    char*  sB = smem + A_BYTES;
    int* s_lreid = (int*)(smem + SM_META_OFF);
    int* s_lr    = s_lreid + 128;
    int* s_v2    = s_lr + 128;
    int* s_pcnt  = s_v2 + 128;

    const uint32_t sA_a = smem_u32(sA);
    const uint32_t sB_a = smem_u32(sB);

    int tid = threadIdx.x;
    int wid = tid >> 5, lane = tid & 31;
    int qid = lane >> 2, tg = lane & 3;
    int mw = wid >> 2, nw = wid & 3;
    int m0 = blockIdx.x * TILE_M;
    int chunk = blockIdx.y;

    // per-row metadata
    if (tid < 128) {
        int m = m0 + tid;
        int t = roi_label[m] - 1;
        bool v = (t >= 0);
        int label = v ? t : 0;
        int lreid = reid_labels[label];
        bool v2 = v && (lreid >= 0);
        s_lreid[tid] = lreid;
        s_lr[tid] = lreid > 0 ? lreid : 0;
        s_v2[tid] = v2 ? 1 : 0;
        s_pcnt[tid] = 0;
    }

    // ---- stage A (32 chunks/thread) + B stage 0, then B stage 1 ----
    {
#pragma unroll
        for (int j = 0; j < 32; j++) {
            int ci = tid + j * 256;
            int row = ci >> 6, kc = ci & 63;
            cp16(sA_a + (uint32_t)(row * AS + kc * 4) * 4,
                 inputs + (size_t)(m0 + row) * NF + kc * 4, 16);
        }
    }
    auto issue_B = [&](int i) {
        int nt = i >> 3, s = i & 7, buf = i & 1;
        const float* lut = (nt < 4) ? lut_inst : reid_lut;
        int p0 = chunk * CHUNK_P + (nt & 3) * 256;
        uint32_t dstBase = sB_a + (uint32_t)buf * B_STAGE_BYTES;
#pragma unroll
        for (int j = 0; j < 8; j++) {
            int ci = tid + j * 256;
            int row = ci >> 3, kc = ci & 7;
            int p = p0 + row;
            int pc = p < NP ? p : NP - 1;
            cp16(dstBase + (uint32_t)(row * BS + kc * 4) * 4,
                 lut + (size_t)pc * NF + s * 32 + kc * 4,
                 (p < NP) ? 16 : 0);
        }
    };
    issue_B(0);
    CP_COMMIT();
    issue_B(1);
    CP_COMMIT();

    float acc[4][8][4];
    float sneg[8], sall[8];
#pragma unroll
    for (int q = 0; q < 8; q++) { sneg[q] = 0.0f; sall[q] = 0.0f; }

    const uint32_t* Ab = (const uint32_t*)sA;

#pragma unroll 1
    for (int i = 0; i < 64; i++) {
        int nt = i >> 3, s = i & 7, buf = i & 1;
        if (s == 0) {
#pragma unroll
            for (int mf = 0; mf < 4; mf++)
#pragma unroll
                for (int nf = 0; nf < 8; nf++)
#pragma unroll
                    for (int r = 0; r < 4; r++) acc[mf][nf][r] = 0.0f;
        }
        CP_WAIT1();
        __syncthreads();

        const uint32_t* Bb = (const uint32_t*)(sB + buf * B_STAGE_BYTES);
#pragma unroll
        for (int kk = 0; kk < 4; kk++) {
            int k0 = s * 32 + kk * 8 + tg;
            uint32_t a[4][4];
#pragma unroll
            for (int mf = 0; mf < 4; mf++) {
                int r = mw * 64 + mf * 16 + qid;
                a[mf][0] = Ab[r * AS + k0];
                a[mf][1] = Ab[(r + 8) * AS + k0];
                a[mf][2] = Ab[r * AS + k0 + 4];
                a[mf][3] = Ab[(r + 8) * AS + k0 + 4];
            }
#pragma unroll
            for (int nf = 0; nf < 8; nf++) {
                int n = nw * 64 + nf * 8 + qid;
                uint32_t b0 = Bb[n * BS + kk * 8 + tg];
                uint32_t b1 = Bb[n * BS + kk * 8 + tg + 4];
#pragma unroll
                for (int mf = 0; mf < 4; mf++)
                    mma8(acc[mf][nf], a[mf], b0, b1);
            }
        }
        __syncthreads();
        if (i + 2 < 64) issue_B(i + 2);
        CP_COMMIT();

        if (s == 7) {
            // ---------------- epilogue for ntile nt ----------------
            int p0 = chunk * CHUNK_P + (nt & 3) * 256;
            if (nt < 4) {
#pragma unroll
                for (int nf = 0; nf < 8; nf++) {
                    int pb = p0 + nw * 64 + nf * 8 + tg * 2;
                    int pc0 = pb < NP ? pb : NP - 1;
                    int pc1 = pb + 1 < NP ? pb + 1 : NP - 1;
                    int rl0 = __ldg(&reid_labels[pc0]);
                    int rl1 = __ldg(&reid_labels[pc1]);
                    bool ok0 = pb < NP, ok1 = (pb + 1) < NP;
#pragma unroll
                    for (int mf = 0; mf < 4; mf++) {
#pragma unroll
                        for (int h = 0; h < 2; h++) {
                            int lrow = mw * 64 + mf * 16 + h * 8 + qid;
                            int lre = s_lreid[lrow];
                            int slot = mf * 2 + h;
                            float x0 = acc[mf][nf][h * 2 + 0] * 30.0f;
                            float x1 = acc[mf][nf][h * 2 + 1] * 30.0f;
                            if (ok0) {
                                if (rl0 == lre) {
                                    if (s_v2[lrow]) {
                                        int idx = atomicAdd(&s_pcnt[lrow], 1);
                                        if (idx < CAPC) {
                                            int base = ((m0 + lrow) * NCHUNK + chunk) * CAPC + idx;
                                            g_posx[base] = x0;
                                            g_posp[base] = pb;
                                        }
                                    }
                                } else sneg[slot] += __expf(x0 - 30.0f);
                            }
                            if (ok1) {
                                if (rl1 == lre) {
                                    if (s_v2[lrow]) {
                                        int idx = atomicAdd(&s_pcnt[lrow], 1);
                                        if (idx < CAPC) {
                                            int base = ((m0 + lrow) * NCHUNK + chunk) * CAPC + idx;
                                            g_posx[base] = x1;
                                            g_posp[base] = pb + 1;
                                        }
                                    }
                                } else sneg[slot] += __expf(x1 - 30.0f);
                            }
                        }
                    }
                }
            } else {
#pragma unroll
                for (int nf = 0; nf < 8; nf++) {
                    int pb = p0 + nw * 64 + nf * 8 + tg * 2;
                    bool ok0 = pb < NP, ok1 = (pb + 1) < NP;
#pragma unroll
                    for (int mf = 0; mf < 4; mf++) {
#pragma unroll
                        for (int h = 0; h < 2; h++) {
                            int lrow = mw * 64 + mf * 16 + h * 8 + qid;
                            int slot = mf * 2 + h;
                            float x0 = acc[mf][nf][h * 2 + 0] * 30.0f;
                            float x1 = acc[mf][nf][h * 2 + 1] * 30.0f;
                            if (ok0) {
                                sall[slot] += __expf(x0 - 30.0f);
                                if (pb == s_lr[lrow]) g_xt[m0 + lrow] = x0;
                            }
                            if (ok1) {
                                sall[slot] += __expf(x1 - 30.0f);
                                if (pb + 1 == s_lr[lrow]) g_xt[m0 + lrow] = x1;
                            }
                        }
                    }
                }
            }
            if (nt == 3 || nt == 7) {
                float* arr = (nt == 3) ? sneg : sall;
#pragma unroll
                for (int slot = 0; slot < 8; slot++) {
                    float v = arr[slot];
                    v += __shfl_xor_sync(0xffffffffu, v, 1);
                    v += __shfl_xor_sync(0xffffffffu, v, 2);
                    if (tg == 0) {
                        int mf = slot >> 1, h = slot & 1;
                        int lrow = mw * 64 + mf * 16 + h * 8 + qid;
                        int m = m0 + lrow;
                        if (nt == 3)
                            g_s_inst[(m * NCHUNK + chunk) * 4 + nw] = v;
                        else
                            g_s_reid[(m * NCHUNK + chunk) * 4 + nw] = v;
                    }
                }
            }
        }
    }

    __syncthreads();
    if (tid < 128)
        g_pcnt[(m0 + tid) * NCHUNK + chunk] = s_pcnt[tid];
}

// ---------------------------------------------------------------------------
// Feature-consistency partials
// ---------------------------------------------------------------------------
__global__ void __launch_bounds__(256)
fc_kernel(const float* __restrict__ inputs, const int* __restrict__ roi_label,
          const float* __restrict__ lut_inst)
{
    __shared__ float sred[8];
    int tid = threadIdx.x, wid = tid >> 5, lane = tid & 31;
    int m0 = blockIdx.x * 128;
    float acc = 0.0f;
    for (int r = wid; r < 128; r += 8) {
        int m = m0 + r;
        int t = roi_label[m] - 1;
        if (t >= 0) {
            const float4* a = (const float4*)(inputs + (size_t)m * NF);
            const float4* b = (const float4*)(lut_inst + (size_t)t * NF);
            float s = 0.0f;
#pragma unroll
            for (int i = 0; i < 2; i++) {
                float4 av = a[lane + 32 * i], bv = b[lane + 32 * i];
                float dx = bv.x - av.x, dy = bv.y - av.y;
                float dz = bv.z - av.z, dw = bv.w - av.w;
                s += dx * dx + dy * dy + dz * dz + dw * dw;
            }
#pragma unroll
            for (int o = 16; o; o >>= 1) s += __shfl_xor_sync(0xffffffffu, s, o);
            acc += s;
        }
    }
    if (lane == 0) sred[wid] = acc;
    __syncthreads();
    if (tid == 0) {
        float s = 0.0f;
        for (int w = 0; w < 8; w++) s += sred[w];
        g_fc[blockIdx.x] = s;
    }
}

// ---------------------------------------------------------------------------
// Finalize stage 1: per-row losses -> per-CTA partials (deterministic)
// ---------------------------------------------------------------------------
__global__ void __launch_bounds__(256)
finalize1_kernel(const int* __restrict__ roi_label,
                 const int* __restrict__ reid_labels)
{
    __shared__ float sred[8][5];
    int tid = threadIdx.x, wid = tid >> 5, lane = tid & 31;
    int m0 = blockIdx.x * 128;
    float instS = 0.f, ceS = 0.f, n1 = 0.f, n2 = 0.f, n3 = 0.f;

    for (int r = tid; r < 128; r += 256) {
        int m = m0 + r;
        int t = roi_label[m] - 1;
        bool v = (t >= 0);
        int label = v ? t : 0;
        int lreid = reid_labels[label];
        bool v2 = v && (lreid >= 0);
        int lr = lreid > 0 ? lreid : 0;
        bool v3 = v2 && (lr != IGNORE_INDEX);
        n1 += v ? 1.f : 0.f;
        n2 += v2 ? 1.f : 0.f;
        n3 += v3 ? 1.f : 0.f;
        if (v2) {
            float s = 0.f;
            for (int c = 0; c < NCHUNK; c++)
                for (int w = 0; w < 4; w++)
                    s += g_s_inst[(m * NCHUNK + c) * 4 + w];
            float lse = (s > 0.f) ? (30.f + logf(s)) : -1e30f;
            int cnt = 0;
            float sum = 0.f;
            for (int c = 0; c < NCHUNK; c++) {
                int pc = g_pcnt[m * NCHUNK + c];
                cnt += pc;
                int pl = pc < CAPC ? pc : CAPC;
                if (pl == 1) {
                    sum += log1pf(expf(lse - g_posx[(m * NCHUNK + c) * CAPC]));
                } else if (pl > 1) {
                    int pp[CAPC];
                    float xx[CAPC];
                    for (int q = 0; q < pl; q++) {
                        pp[q] = g_posp[(m * NCHUNK + c) * CAPC + q];
                        xx[q] = g_posx[(m * NCHUNK + c) * CAPC + q];
                    }
                    for (int it = 0; it < pl; it++) {   // ascending-p order
                        int bj = 0, bp = 0x7fffffff;
                        for (int q = 0; q < pl; q++)
                            if (pp[q] < bp) { bp = pp[q]; bj = q; }
                        sum += log1pf(expf(lse - xx[bj]));
                        pp[bj] = 0x7fffffff;
                    }
                }
            }
            instS += sum / fmaxf((float)cnt, 1.f);
            if (v3) {
                float s2 = 0.f;
                for (int c = 0; c < NCHUNK; c++)
                    for (int w = 0; w < 4; w++)
                        s2 += g_s_reid[(m * NCHUNK + c) * 4 + w];
                ceS += (30.f + logf(s2)) - g_xt[m];
            }
        }
    }
    float vals[5] = {instS, ceS, n1, n2, n3};
#pragma unroll
    for (int k = 0; k < 5; k++)
#pragma unroll
        for (int o = 16; o; o >>= 1)
            vals[k] += __shfl_xor_sync(0xffffffffu, vals[k], o);
    if (lane == 0)
        for (int k = 0; k < 5; k++) sred[wid][k] = vals[k];
    __syncthreads();
    if (tid == 0) {
        float tot[5] = {0, 0, 0, 0, 0};
        for (int w = 0; w < 8; w++)
            for (int k = 0; k < 5; k++) tot[k] += sred[w][k];
        for (int k = 0; k < 5; k++) g_part[blockIdx.x][k] = tot[k];
    }
}

// ---------------------------------------------------------------------------
// Finalize stage 2: combine partials -> scalar
// ---------------------------------------------------------------------------
__global__ void finalize2_kernel(float* __restrict__ out) {
    if (threadIdx.x == 0) {
        float tot[5] = {0, 0, 0, 0, 0};
        for (int b = 0; b < NMTILE; b++)
            for (int k = 0; k < 5; k++) tot[k] += g_part[b][k];
        float fc = 0.f;
        for (int b = 0; b < NMTILE; b++) fc += g_fc[b];
        out[0] = fc / (fmaxf(tot[2], 1.f) * (float)NF)
               + tot[1] / fmaxf(tot[4], 1.f)
               + tot[0] / fmaxf(tot[3], 1.f);
    }
}

// ---------------------------------------------------------------------------
extern "C" void kernel_launch(void* const* d_in, const int* in_sizes, int n_in,
                              void* d_out, int out_size) {
    const float* inputs      = (const float*)d_in[0];
    const int*   roi_label   = (const int*)d_in[1];
    const float* lut_inst    = (const float*)d_in[2];
    const float* reid_lut    = (const float*)d_in[3];
    const int*   reid_labels = (const int*)d_in[4];
    float* out = (float*)d_out;

    cudaFuncSetAttribute(main_kernel, cudaFuncAttributeMaxDynamicSharedMemorySize,
                         SMEM_TOTAL);

    fc_kernel<<<NMTILE, 256>>>(inputs, roi_label, lut_inst);
    main_kernel<<<dim3(NMTILE, NCHUNK), 256, SMEM_TOTAL>>>(
        inputs, roi_label, lut_inst, reid_lut, reid_labels);
    finalize1_kernel<<<NMTILE, 256>>>(roi_label, reid_labels);
    finalize2_kernel<<<1, 32>>>(out);
}

// round 4
// speedup vs baseline: 3.4867x; 1.3241x over previous
#include <cuda_runtime.h>
#include <cuda_fp16.h>
#include <math.h>
#include <stdint.h>

#define NB 4096
#define NF 256
#define NP 5000
#define NCHUNK 4
#define CHUNK_P 1280
#define NMTILE 32
#define CAPC 16
#define IGNORE_INDEX 5554
#define AST 264                       // A smem row stride (halfs), 528B
#define BST 72                        // B smem row stride (halfs), 144B
#define A_BYTES (128 * AST * 2)       // 67584
#define B_STAGE (256 * BST * 2)       // 36864
#define SM_META (A_BYTES + 2 * B_STAGE)
#define SMEM_TOTAL (SM_META + 4 * 128 * 4)
#define NI 40                         // 10 nt-tiles * 4 k-chunks

// ---------------- static scratch ----------------
__device__ __align__(16) __half g_inh[NB * NF];
__device__ __align__(16) __half g_lih[NP * NF];
__device__ __align__(16) __half g_rlh[NP * NF];
__device__ float g_s_inst[NB * NCHUNK * 8];
__device__ float g_s_reid[NB * NCHUNK * 8];
__device__ int   g_pcnt[NB * NCHUNK];
__device__ float g_posx[NB * NCHUNK * CAPC];
__device__ int   g_posp[NB * NCHUNK * CAPC];
__device__ float g_xt[NB];
__device__ float g_fc[NMTILE];

// ---------------- helpers ----------------
__device__ __forceinline__ uint32_t smem_u32(const void* p) {
    uint32_t a;
    asm("{ .reg .u64 t; cvta.to.shared.u64 t, %1; cvt.u32.u64 %0, t; }"
        : "=r"(a) : "l"(p));
    return a;
}
__device__ __forceinline__ void cp16(uint32_t dst, const void* src, int sz) {
    asm volatile("cp.async.cg.shared.global [%0], [%1], 16, %2;"
                 :: "r"(dst), "l"(src), "r"(sz) : "memory");
}
#define CP_COMMIT() asm volatile("cp.async.commit_group;" ::: "memory")
#define CP_WAIT1()  asm volatile("cp.async.wait_group 1;" ::: "memory")

__device__ __forceinline__ void ldmx4(uint32_t* r, uint32_t addr) {
    asm volatile("ldmatrix.sync.aligned.m8n8.x4.shared.b16 {%0,%1,%2,%3}, [%4];"
                 : "=r"(r[0]), "=r"(r[1]), "=r"(r[2]), "=r"(r[3]) : "r"(addr));
}
__device__ __forceinline__ void mma16(float* c, const uint32_t* a,
                                      uint32_t b0, uint32_t b1) {
    asm("mma.sync.aligned.m16n8k16.row.col.f32.f16.f16.f32 "
        "{%0,%1,%2,%3}, {%4,%5,%6,%7}, {%8,%9}, {%0,%1,%2,%3};"
        : "+f"(c[0]), "+f"(c[1]), "+f"(c[2]), "+f"(c[3])
        : "r"(a[0]), "r"(a[1]), "r"(a[2]), "r"(a[3]), "r"(b0), "r"(b1));
}

// ---------------------------------------------------------------------------
// Convert f32 -> f16 scratch
// ---------------------------------------------------------------------------
__global__ void __launch_bounds__(256)
convert_kernel(const float* __restrict__ inp, const float* __restrict__ li,
               const float* __restrict__ rl)
{
    int idx = blockIdx.x * blockDim.x + threadIdx.x;
    int stride = blockDim.x * gridDim.x;
    {
        const float4* a = (const float4*)inp;
        half2* o = (half2*)g_inh;
        for (int i = idx; i < NB * NF / 4; i += stride) {
            float4 v = a[i];
            o[2 * i]     = __floats2half2_rn(v.x, v.y);
            o[2 * i + 1] = __floats2half2_rn(v.z, v.w);
        }
    }
    {
        const float4* a = (const float4*)li;
        half2* o = (half2*)g_lih;
        for (int i = idx; i < NP * NF / 4; i += stride) {
            float4 v = a[i];
            o[2 * i]     = __floats2half2_rn(v.x, v.y);
            o[2 * i + 1] = __floats2half2_rn(v.z, v.w);
        }
    }
    {
        const float4* a = (const float4*)rl;
        half2* o = (half2*)g_rlh;
        for (int i = idx; i < NP * NF / 4; i += stride) {
            float4 v = a[i];
            o[2 * i]     = __floats2half2_rn(v.x, v.y);
            o[2 * i + 1] = __floats2half2_rn(v.z, v.w);
        }
    }
}

// ---------------------------------------------------------------------------
// Main fused kernel: grid (32 m-tiles, 4 p-chunks) = 128 CTAs, 512 threads.
// Warp grid 2(m) x 8(n); warp tile 64x32. nt 0-4: instance LUT, 5-9: reid LUT.
// ---------------------------------------------------------------------------
__global__ void __launch_bounds__(512, 1)
main_kernel(const int* __restrict__ roi_label, const int* __restrict__ reid_labels)
{
    extern __shared__ char smem[];
    char* sB = smem + A_BYTES;
    int* s_lreid = (int*)(smem + SM_META);
    int* s_lr    = s_lreid + 128;
    int* s_v2    = s_lr + 128;
    int* s_pcnt  = s_v2 + 128;

    const uint32_t sA_a = smem_u32(smem);
    const uint32_t sB_a = smem_u32(sB);

    int tid = threadIdx.x;
    int wid = tid >> 5, lane = tid & 31;
    int qid = lane >> 2, tg = lane & 3;
    int mw = wid >> 3, nw = wid & 7;
    int m0 = blockIdx.x * 128;
    int chunk = blockIdx.y;

    if (tid < 128) {
        int m = m0 + tid;
        int t = roi_label[m] - 1;
        bool v = (t >= 0);
        int label = v ? t : 0;
        int lreid = reid_labels[label];
        s_lreid[tid] = lreid;
        s_lr[tid] = lreid > 0 ? lreid : 0;
        s_v2[tid] = (v && lreid >= 0) ? 1 : 0;
        s_pcnt[tid] = 0;
    }

    // ---- stage A (f16, full 128x256) ----
    {
        const __half* Ain = g_inh + (size_t)m0 * NF;
#pragma unroll
        for (int j = 0; j < 8; j++) {
            int ci = tid + j * 512;
            int row = ci >> 5, c = ci & 31;
            cp16(sA_a + (uint32_t)(row * AST + c * 8) * 2, Ain + row * NF + c * 8, 16);
        }
    }
    auto issue_B = [&](int i) {
        int nt = i >> 2, kc = i & 3, buf = i & 1;
        const __half* lut = (nt < 5) ? g_lih : g_rlh;
        int p0 = chunk * CHUNK_P + (nt % 5) * 256;
        uint32_t dstBase = sB_a + (uint32_t)buf * B_STAGE;
#pragma unroll
        for (int j = 0; j < 4; j++) {
            int ci = tid + j * 512;
            int row = ci >> 3, c = ci & 7;
            int p = p0 + row;
            int pc = p < NP ? p : NP - 1;
            cp16(dstBase + (uint32_t)(row * BST + c * 8) * 2,
                 lut + (size_t)pc * NF + kc * 64 + c * 8, (p < NP) ? 16 : 0);
        }
    };
    issue_B(0);
    CP_COMMIT();
    issue_B(1);
    CP_COMMIT();

    // ldmatrix lane bases
    uint32_t abase[4];
#pragma unroll
    for (int mf = 0; mf < 4; mf++)
        abase[mf] = sA_a + (uint32_t)((mw * 64 + mf * 16 + (lane & 15)) * AST
                                      + (lane >> 4) * 8) * 2;
    int noff = (lane & 7) + ((lane >> 4) << 3);
    uint32_t bbase = sB_a + (uint32_t)((nw * 32 + noff) * BST + ((lane & 8) ? 8 : 0)) * 2;

    float acc[4][4][4];
    float sacc[8];
#pragma unroll
    for (int q = 0; q < 8; q++) sacc[q] = 0.0f;

#pragma unroll 1
    for (int i = 0; i < NI; i++) {
        int nt = i >> 2, kc = i & 3, buf = i & 1;
        if (kc == 0) {
#pragma unroll
            for (int mf = 0; mf < 4; mf++)
#pragma unroll
                for (int nf = 0; nf < 4; nf++)
#pragma unroll
                    for (int r = 0; r < 4; r++) acc[mf][nf][r] = 0.0f;
        }
        CP_WAIT1();
        __syncthreads();

        uint32_t bstage = bbase + (uint32_t)buf * B_STAGE;
#pragma unroll
        for (int kk = 0; kk < 4; kk++) {
            uint32_t a[4][4], b[8];
            uint32_t akb = (uint32_t)(kc * 4 + kk) * 32;
#pragma unroll
            for (int mf = 0; mf < 4; mf++) ldmx4(a[mf], abase[mf] + akb);
            ldmx4(b,     bstage + kk * 32);
            ldmx4(b + 4, bstage + 16 * BST * 2 + kk * 32);
#pragma unroll
            for (int nf = 0; nf < 4; nf++)
#pragma unroll
                for (int mf = 0; mf < 4; mf++)
                    mma16(acc[mf][nf], a[mf], b[nf * 2], b[nf * 2 + 1]);
        }
        __syncthreads();
        if (i + 2 < NI) issue_B(i + 2);
        CP_COMMIT();

        if (kc == 3) {
            // ---------------- epilogue for tile nt ----------------
            int p0 = chunk * CHUNK_P + (nt % 5) * 256;
            bool inst = (nt < 5);
#pragma unroll
            for (int nf = 0; nf < 4; nf++) {
                int pb = p0 + nw * 32 + nf * 8 + tg * 2;
                bool ok0 = pb < NP, ok1 = (pb + 1) < NP;
                int rl0 = 0, rl1 = 0;
                if (inst) {
                    rl0 = __ldg(&reid_labels[ok0 ? pb : NP - 1]);
                    rl1 = __ldg(&reid_labels[ok1 ? pb + 1 : NP - 1]);
                }
#pragma unroll
                for (int mf = 0; mf < 4; mf++) {
#pragma unroll
                    for (int h = 0; h < 2; h++) {
                        int lrow = mw * 64 + mf * 16 + h * 8 + qid;
                        int slot = mf * 2 + h;
                        float x0 = acc[mf][nf][h * 2 + 0] * 30.0f;
                        float x1 = acc[mf][nf][h * 2 + 1] * 30.0f;
                        if (inst) {
                            int lre = s_lreid[lrow];
                            if (ok0) {
                                if (rl0 == lre) {
                                    if (s_v2[lrow]) {
                                        int idx = atomicAdd(&s_pcnt[lrow], 1);
                                        if (idx < CAPC) {
                                            int base = ((m0 + lrow) * NCHUNK + chunk) * CAPC + idx;
                                            g_posx[base] = x0;
                                            g_posp[base] = pb;
                                        }
                                    }
                                } else sacc[slot] += __expf(x0 - 30.0f);
                            }
                            if (ok1) {
                                if (rl1 == lre) {
                                    if (s_v2[lrow]) {
                                        int idx = atomicAdd(&s_pcnt[lrow], 1);
                                        if (idx < CAPC) {
                                            int base = ((m0 + lrow) * NCHUNK + chunk) * CAPC + idx;
                                            g_posx[base] = x1;
                                            g_posp[base] = pb + 1;
                                        }
                                    }
                                } else sacc[slot] += __expf(x1 - 30.0f);
                            }
                        } else {
                            if (ok0) {
                                sacc[slot] += __expf(x0 - 30.0f);
                                if (pb == s_lr[lrow]) g_xt[m0 + lrow] = x0;
                            }
                            if (ok1) {
                                sacc[slot] += __expf(x1 - 30.0f);
                                if (pb + 1 == s_lr[lrow]) g_xt[m0 + lrow] = x1;
                            }
                        }
                    }
                }
            }
            if (nt == 4 || nt == 9) {
#pragma unroll
                for (int slot = 0; slot < 8; slot++) {
                    float v = sacc[slot];
                    v += __shfl_xor_sync(0xffffffffu, v, 1);
                    v += __shfl_xor_sync(0xffffffffu, v, 2);
                    if (tg == 0) {
                        int mf = slot >> 1, h = slot & 1;
                        int lrow = mw * 64 + mf * 16 + h * 8 + qid;
                        int m = m0 + lrow;
                        if (nt == 4)
                            g_s_inst[(m * NCHUNK + chunk) * 8 + nw] = v;
                        else
                            g_s_reid[(m * NCHUNK + chunk) * 8 + nw] = v;
                    }
                    sacc[slot] = 0.0f;
                }
            }
        }
    }

    __syncthreads();
    if (tid < 128)
        g_pcnt[(m0 + tid) * NCHUNK + chunk] = s_pcnt[tid];
}

// ---------------------------------------------------------------------------
// Feature-consistency partials (exact f32)
// ---------------------------------------------------------------------------
__global__ void __launch_bounds__(256)
fc_kernel(const float* __restrict__ inputs, const int* __restrict__ roi_label,
          const float* __restrict__ lut_inst)
{
    __shared__ float sred[8];
    int tid = threadIdx.x, wid = tid >> 5, lane = tid & 31;
    int m0 = blockIdx.x * 128;
    float acc = 0.0f;
    for (int r = wid; r < 128; r += 8) {
        int m = m0 + r;
        int t = roi_label[m] - 1;
        if (t >= 0) {
            const float4* a = (const float4*)(inputs + (size_t)m * NF);
            const float4* b = (const float4*)(lut_inst + (size_t)t * NF);
            float s = 0.0f;
#pragma unroll
            for (int i = 0; i < 2; i++) {
                float4 av = a[lane + 32 * i], bv = b[lane + 32 * i];
                float dx = bv.x - av.x, dy = bv.y - av.y;
                float dz = bv.z - av.z, dw = bv.w - av.w;
                s += dx * dx + dy * dy + dz * dz + dw * dw;
            }
#pragma unroll
            for (int o = 16; o; o >>= 1) s += __shfl_xor_sync(0xffffffffu, s, o);
            acc += s;
        }
    }
    if (lane == 0) sred[wid] = acc;
    __syncthreads();
    if (tid == 0) {
        float s = 0.0f;
        for (int w = 0; w < 8; w++) s += sred[w];
        g_fc[blockIdx.x] = s;
    }
}

// ---------------------------------------------------------------------------
// Finalize: 1 CTA, per-row losses + global reduction -> scalar
// ---------------------------------------------------------------------------
__global__ void __launch_bounds__(1024)
finalize_kernel(const int* __restrict__ roi_label,
                const int* __restrict__ reid_labels, float* __restrict__ out)
{
    __shared__ float sred[32][5];
    int tid = threadIdx.x, wid = tid >> 5, lane = tid & 31;
    float instS = 0.f, ceS = 0.f, n1 = 0.f, n2 = 0.f, n3 = 0.f;

    for (int m = tid; m < NB; m += 1024) {
        int t = roi_label[m] - 1;
        bool v = (t >= 0);
        int label = v ? t : 0;
        int lreid = reid_labels[label];
        bool v2 = v && (lreid >= 0);
        int lr = lreid > 0 ? lreid : 0;
        bool v3 = v2 && (lr != IGNORE_INDEX);
        n1 += v ? 1.f : 0.f;
        n2 += v2 ? 1.f : 0.f;
        n3 += v3 ? 1.f : 0.f;
        if (v2) {
            float s = 0.f;
            for (int c = 0; c < NCHUNK; c++)
                for (int w = 0; w < 8; w++)
                    s += g_s_inst[(m * NCHUNK + c) * 8 + w];
            float lse = (s > 0.f) ? (30.f + logf(s)) : -1e30f;
            int cnt = 0;
            float sum = 0.f;
            for (int c = 0; c < NCHUNK; c++) {
                int pc = g_pcnt[m * NCHUNK + c];
                cnt += pc;
                int pl = pc < CAPC ? pc : CAPC;
                if (pl == 1) {
                    sum += log1pf(expf(lse - g_posx[(m * NCHUNK + c) * CAPC]));
                } else if (pl > 1) {
                    int pp[CAPC];
                    float xx[CAPC];
                    for (int q = 0; q < pl; q++) {
                        pp[q] = g_posp[(m * NCHUNK + c) * CAPC + q];
                        xx[q] = g_posx[(m * NCHUNK + c) * CAPC + q];
                    }
                    for (int it = 0; it < pl; it++) {   // ascending-p order
                        int bj = 0, bp = 0x7fffffff;
                        for (int q = 0; q < pl; q++)
                            if (pp[q] < bp) { bp = pp[q]; bj = q; }
                        sum += log1pf(expf(lse - xx[bj]));
                        pp[bj] = 0x7fffffff;
                    }
                }
            }
            instS += sum / fmaxf((float)cnt, 1.f);
            if (v3) {
                float s2 = 0.f;
                for (int c = 0; c < NCHUNK; c++)
                    for (int w = 0; w < 8; w++)
                        s2 += g_s_reid[(m * NCHUNK + c) * 8 + w];
                ceS += (30.f + logf(s2)) - g_xt[m];
            }
        }
    }
    float vals[5] = {instS, ceS, n1, n2, n3};
#pragma unroll
    for (int k = 0; k < 5; k++)
#pragma unroll
        for (int o = 16; o; o >>= 1)
            vals[k] += __shfl_xor_sync(0xffffffffu, vals[k], o);
    if (lane == 0)
        for (int k = 0; k < 5; k++) sred[wid][k] = vals[k];
    __syncthreads();
    if (tid == 0) {
        float tot[5] = {0, 0, 0, 0, 0};
        for (int w = 0; w < 32; w++)
            for (int k = 0; k < 5; k++) tot[k] += sred[w][k];
        float fc = 0.f;
        for (int b = 0; b < NMTILE; b++) fc += g_fc[b];
        out[0] = fc / (fmaxf(tot[2], 1.f) * (float)NF)
               + tot[1] / fmaxf(tot[4], 1.f)
               + tot[0] / fmaxf(tot[3], 1.f);
    }
}

// ---------------------------------------------------------------------------
extern "C" void kernel_launch(void* const* d_in, const int* in_sizes, int n_in,
                              void* d_out, int out_size) {
    const float* inputs      = (const float*)d_in[0];
    const int*   roi_label   = (const int*)d_in[1];
    const float* lut_inst    = (const float*)d_in[2];
    const float* reid_lut    = (const float*)d_in[3];
    const int*   reid_labels = (const int*)d_in[4];
    float* out = (float*)d_out;

    cudaFuncSetAttribute(main_kernel, cudaFuncAttributeMaxDynamicSharedMemorySize,
                         SMEM_TOTAL);

    convert_kernel<<<128, 256>>>(inputs, lut_inst, reid_lut);
    fc_kernel<<<NMTILE, 256>>>(inputs, roi_label, lut_inst);
    main_kernel<<<dim3(NMTILE, NCHUNK), 512, SMEM_TOTAL>>>(roi_label, reid_labels);
    finalize_kernel<<<1, 1024>>>(roi_label, reid_labels, out);
}

// round 5
// speedup vs baseline: 6.8721x; 1.9710x over previous
#include <cuda_runtime.h>
#include <cuda_fp16.h>
#include <math.h>
#include <stdint.h>

#define NB 4096
#define NF 256
#define NP 5000
#define NCHUNK 4
#define CHUNK_P 1280
#define NMTILE 32
#define CAPC 16
#define IGNORE_INDEX 5554
#define AST 264                       // A smem row stride (halfs), 528B
#define BST 72                        // B smem row stride (halfs), 144B
#define A_BYTES (128 * AST * 2)       // 67584
#define B_STAGE (256 * BST * 2)       // 36864
#define NSTAGE 3
#define SM_META (A_BYTES + NSTAGE * B_STAGE)
#define SMEM_TOTAL (SM_META + 4 * 128 * 4)
#define NI 40                         // 10 nt-tiles * 4 k-chunks

// ---------------- static scratch ----------------
__device__ __align__(16) __half g_inh[NB * NF];
__device__ __align__(16) __half g_lih[NP * NF];
__device__ __align__(16) __half g_rlh[NP * NF];
__device__ float g_s_inst[NB * NCHUNK * 8];
__device__ float g_s_reid[NB * NCHUNK * 8];
__device__ int   g_pcnt[NB * NCHUNK];
__device__ float g_posx[NB * NCHUNK * CAPC];
__device__ float g_xt[NB];
__device__ float g_fc[NMTILE];
__device__ float g_part[NMTILE][5];

// ---------------- helpers ----------------
__device__ __forceinline__ uint32_t smem_u32(const void* p) {
    uint32_t a;
    asm("{ .reg .u64 t; cvta.to.shared.u64 t, %1; cvt.u32.u64 %0, t; }"
        : "=r"(a) : "l"(p));
    return a;
}
__device__ __forceinline__ void cp16(uint32_t dst, const void* src, int sz) {
    asm volatile("cp.async.cg.shared.global [%0], [%1], 16, %2;"
                 :: "r"(dst), "l"(src), "r"(sz) : "memory");
}
#define CP_COMMIT() asm volatile("cp.async.commit_group;" ::: "memory")
#define CP_WAIT2()  asm volatile("cp.async.wait_group 2;" ::: "memory")

__device__ __forceinline__ void ldmx4(uint32_t* r, uint32_t addr) {
    asm volatile("ldmatrix.sync.aligned.m8n8.x4.shared.b16 {%0,%1,%2,%3}, [%4];"
                 : "=r"(r[0]), "=r"(r[1]), "=r"(r[2]), "=r"(r[3]) : "r"(addr));
}
__device__ __forceinline__ void mma16(float* c, const uint32_t* a,
                                      uint32_t b0, uint32_t b1) {
    asm("mma.sync.aligned.m16n8k16.row.col.f32.f16.f16.f32 "
        "{%0,%1,%2,%3}, {%4,%5,%6,%7}, {%8,%9}, {%0,%1,%2,%3};"
        : "+f"(c[0]), "+f"(c[1]), "+f"(c[2]), "+f"(c[3])
        : "r"(a[0]), "r"(a[1]), "r"(a[2]), "r"(a[3]), "r"(b0), "r"(b1));
}

// ---------------------------------------------------------------------------
// Convert f32 -> f16 scratch
// ---------------------------------------------------------------------------
__global__ void __launch_bounds__(256)
convert_kernel(const float* __restrict__ inp, const float* __restrict__ li,
               const float* __restrict__ rl)
{
    int idx = blockIdx.x * blockDim.x + threadIdx.x;
    int stride = blockDim.x * gridDim.x;
    {
        const float4* a = (const float4*)inp;
        half2* o = (half2*)g_inh;
        for (int i = idx; i < NB * NF / 4; i += stride) {
            float4 v = a[i];
            o[2 * i]     = __floats2half2_rn(v.x, v.y);
            o[2 * i + 1] = __floats2half2_rn(v.z, v.w);
        }
    }
    {
        const float4* a = (const float4*)li;
        half2* o = (half2*)g_lih;
        for (int i = idx; i < NP * NF / 4; i += stride) {
            float4 v = a[i];
            o[2 * i]     = __floats2half2_rn(v.x, v.y);
            o[2 * i + 1] = __floats2half2_rn(v.z, v.w);
        }
    }
    {
        const float4* a = (const float4*)rl;
        half2* o = (half2*)g_rlh;
        for (int i = idx; i < NP * NF / 4; i += stride) {
            float4 v = a[i];
            o[2 * i]     = __floats2half2_rn(v.x, v.y);
            o[2 * i + 1] = __floats2half2_rn(v.z, v.w);
        }
    }
}

// ---------------------------------------------------------------------------
// Main fused kernel: grid (32 m-tiles, 4 p-chunks) = 128 CTAs, 512 threads.
// Warp grid 2(m) x 8(n); warp tile 64x32. nt 0-4: instance LUT, 5-9: reid LUT.
// 3-stage cp.async pipeline on B.
// ---------------------------------------------------------------------------
__global__ void __launch_bounds__(512, 1)
main_kernel(const int* __restrict__ roi_label, const int* __restrict__ reid_labels)
{
    extern __shared__ char smem[];
    char* sB = smem + A_BYTES;
    int* s_lreid = (int*)(smem + SM_META);
    int* s_lr    = s_lreid + 128;
    int* s_v2    = s_lr + 128;
    int* s_pcnt  = s_v2 + 128;

    const uint32_t sA_a = smem_u32(smem);
    const uint32_t sB_a = smem_u32(sB);

    int tid = threadIdx.x;
    int wid = tid >> 5, lane = tid & 31;
    int qid = lane >> 2, tg = lane & 3;
    int mw = wid >> 3, nw = wid & 7;
    int m0 = blockIdx.x * 128;
    int chunk = blockIdx.y;

    if (tid < 128) {
        int m = m0 + tid;
        int t = roi_label[m] - 1;
        bool v = (t >= 0);
        int label = v ? t : 0;
        int lreid = reid_labels[label];
        s_lreid[tid] = lreid;
        s_lr[tid] = lreid > 0 ? lreid : 0;
        s_v2[tid] = (v && lreid >= 0) ? 1 : 0;
        s_pcnt[tid] = 0;
    }

    // ---- stage A (f16, full 128x256) ----
    {
        const __half* Ain = g_inh + (size_t)m0 * NF;
#pragma unroll
        for (int j = 0; j < 8; j++) {
            int ci = tid + j * 512;
            int row = ci >> 5, c = ci & 31;
            cp16(sA_a + (uint32_t)(row * AST + c * 8) * 2, Ain + row * NF + c * 8, 16);
        }
    }
    auto issue_B = [&](int i, int buf) {
        int nt = i >> 2, kc = i & 3;
        const __half* lut = (nt < 5) ? g_lih : g_rlh;
        int p0 = chunk * CHUNK_P + (nt % 5) * 256;
        uint32_t dstBase = sB_a + (uint32_t)buf * B_STAGE;
#pragma unroll
        for (int j = 0; j < 4; j++) {
            int ci = tid + j * 512;
            int row = ci >> 3, c = ci & 7;
            int p = p0 + row;
            int pc = p < NP ? p : NP - 1;
            cp16(dstBase + (uint32_t)(row * BST + c * 8) * 2,
                 lut + (size_t)pc * NF + kc * 64 + c * 8, (p < NP) ? 16 : 0);
        }
    };
    issue_B(0, 0);
    CP_COMMIT();
    issue_B(1, 1);
    CP_COMMIT();
    issue_B(2, 2);
    CP_COMMIT();

    // ldmatrix lane bases
    uint32_t abase[4];
#pragma unroll
    for (int mf = 0; mf < 4; mf++)
        abase[mf] = sA_a + (uint32_t)((mw * 64 + mf * 16 + (lane & 15)) * AST
                                      + (lane >> 4) * 8) * 2;
    int noff = (lane & 7) + ((lane >> 4) << 3);
    uint32_t bbase = sB_a + (uint32_t)((nw * 32 + noff) * BST + ((lane & 8) ? 8 : 0)) * 2;

    float acc[4][4][4];
    float sacc[8];
#pragma unroll
    for (int q = 0; q < 8; q++) sacc[q] = 0.0f;

    int bufi = 0;
#pragma unroll 1
    for (int i = 0; i < NI; i++) {
        int nt = i >> 2, kc = i & 3;
        if (kc == 0) {
#pragma unroll
            for (int mf = 0; mf < 4; mf++)
#pragma unroll
                for (int nf = 0; nf < 4; nf++)
#pragma unroll
                    for (int r = 0; r < 4; r++) acc[mf][nf][r] = 0.0f;
        }
        CP_WAIT2();
        __syncthreads();

        uint32_t bstage = bbase + (uint32_t)bufi * B_STAGE;
#pragma unroll
        for (int kk = 0; kk < 4; kk++) {
            uint32_t a[4][4], b[8];
            uint32_t akb = (uint32_t)(kc * 4 + kk) * 32;
#pragma unroll
            for (int mf = 0; mf < 4; mf++) ldmx4(a[mf], abase[mf] + akb);
            ldmx4(b,     bstage + kk * 32);
            ldmx4(b + 4, bstage + 16 * BST * 2 + kk * 32);
#pragma unroll
            for (int nf = 0; nf < 4; nf++)
#pragma unroll
                for (int mf = 0; mf < 4; mf++)
                    mma16(acc[mf][nf], a[mf], b[nf * 2], b[nf * 2 + 1]);
        }
        __syncthreads();
        if (i + NSTAGE < NI) issue_B(i + NSTAGE, bufi);
        CP_COMMIT();
        bufi = (bufi == NSTAGE - 1) ? 0 : bufi + 1;

        if (kc == 3) {
            // ---------------- epilogue for tile nt ----------------
            int p0 = chunk * CHUNK_P + (nt % 5) * 256;
            bool inst = (nt < 5);
#pragma unroll
            for (int nf = 0; nf < 4; nf++) {
                int pb = p0 + nw * 32 + nf * 8 + tg * 2;
                bool ok0 = pb < NP, ok1 = (pb + 1) < NP;
                int rl0 = 0, rl1 = 0;
                if (inst) {
                    rl0 = __ldg(&reid_labels[ok0 ? pb : NP - 1]);
                    rl1 = __ldg(&reid_labels[ok1 ? pb + 1 : NP - 1]);
                }
#pragma unroll
                for (int mf = 0; mf < 4; mf++) {
#pragma unroll
                    for (int h = 0; h < 2; h++) {
                        int lrow = mw * 64 + mf * 16 + h * 8 + qid;
                        int slot = mf * 2 + h;
                        float x0 = acc[mf][nf][h * 2 + 0] * 30.0f;
                        float x1 = acc[mf][nf][h * 2 + 1] * 30.0f;
                        if (inst) {
                            int lre = s_lreid[lrow];
                            if (ok0) {
                                if (rl0 == lre) {
                                    if (s_v2[lrow]) {
                                        int idx = atomicAdd(&s_pcnt[lrow], 1);
                                        if (idx < CAPC)
                                            g_posx[((m0 + lrow) * NCHUNK + chunk) * CAPC + idx] = x0;
                                    }
                                } else sacc[slot] += __expf(x0 - 30.0f);
                            }
                            if (ok1) {
                                if (rl1 == lre) {
                                    if (s_v2[lrow]) {
                                        int idx = atomicAdd(&s_pcnt[lrow], 1);
                                        if (idx < CAPC)
                                            g_posx[((m0 + lrow) * NCHUNK + chunk) * CAPC + idx] = x1;
                                    }
                                } else sacc[slot] += __expf(x1 - 30.0f);
                            }
                        } else {
                            if (ok0) {
                                sacc[slot] += __expf(x0 - 30.0f);
                                if (pb == s_lr[lrow]) g_xt[m0 + lrow] = x0;
                            }
                            if (ok1) {
                                sacc[slot] += __expf(x1 - 30.0f);
                                if (pb + 1 == s_lr[lrow]) g_xt[m0 + lrow] = x1;
                            }
                        }
                    }
                }
            }
            if (nt == 4 || nt == 9) {
#pragma unroll
                for (int slot = 0; slot < 8; slot++) {
                    float v = sacc[slot];
                    v += __shfl_xor_sync(0xffffffffu, v, 1);
                    v += __shfl_xor_sync(0xffffffffu, v, 2);
                    if (tg == 0) {
                        int mf = slot >> 1, h = slot & 1;
                        int lrow = mw * 64 + mf * 16 + h * 8 + qid;
                        int m = m0 + lrow;
                        if (nt == 4)
                            g_s_inst[(m * NCHUNK + chunk) * 8 + nw] = v;
                        else
                            g_s_reid[(m * NCHUNK + chunk) * 8 + nw] = v;
                    }
                    sacc[slot] = 0.0f;
                }
            }
        }
    }

    __syncthreads();
    if (tid < 128)
        g_pcnt[(m0 + tid) * NCHUNK + chunk] = s_pcnt[tid];
}

// ---------------------------------------------------------------------------
// Feature-consistency partials (exact f32)
// ---------------------------------------------------------------------------
__global__ void __launch_bounds__(256)
fc_kernel(const float* __restrict__ inputs, const int* __restrict__ roi_label,
          const float* __restrict__ lut_inst)
{
    __shared__ float sred[8];
    int tid = threadIdx.x, wid = tid >> 5, lane = tid & 31;
    int m0 = blockIdx.x * 128;
    float acc = 0.0f;
    for (int r = wid; r < 128; r += 8) {
        int m = m0 + r;
        int t = roi_label[m] - 1;
        if (t >= 0) {
            const float4* a = (const float4*)(inputs + (size_t)m * NF);
            const float4* b = (const float4*)(lut_inst + (size_t)t * NF);
            float s = 0.0f;
#pragma unroll
            for (int i = 0; i < 2; i++) {
                float4 av = a[lane + 32 * i], bv = b[lane + 32 * i];
                float dx = bv.x - av.x, dy = bv.y - av.y;
                float dz = bv.z - av.z, dw = bv.w - av.w;
                s += dx * dx + dy * dy + dz * dz + dw * dw;
            }
#pragma unroll
            for (int o = 16; o; o >>= 1) s += __shfl_xor_sync(0xffffffffu, s, o);
            acc += s;
        }
    }
    if (lane == 0) sred[wid] = acc;
    __syncthreads();
    if (tid == 0) {
        float s = 0.0f;
        for (int w = 0; w < 8; w++) s += sred[w];
        g_fc[blockIdx.x] = s;
    }
}

// ---------------------------------------------------------------------------
// Finalize stage 1: 32 CTAs x 128 threads, one row per thread
// ---------------------------------------------------------------------------
__global__ void __launch_bounds__(128)
finalize1_kernel(const int* __restrict__ roi_label,
                 const int* __restrict__ reid_labels)
{
    __shared__ float sred[4][5];
    int tid = threadIdx.x, wid = tid >> 5, lane = tid & 31;
    int m = blockIdx.x * 128 + tid;

    int t = roi_label[m] - 1;
    bool v = (t >= 0);
    int label = v ? t : 0;
    int lreid = reid_labels[label];
    bool v2 = v && (lreid >= 0);
    int lr = lreid > 0 ? lreid : 0;
    bool v3 = v2 && (lr != IGNORE_INDEX);

    float instS = 0.f, ceS = 0.f;
    if (v2) {
        float s = 0.f;
#pragma unroll
        for (int c = 0; c < NCHUNK; c++)
#pragma unroll
            for (int w = 0; w < 8; w++)
                s += g_s_inst[(m * NCHUNK + c) * 8 + w];
        float lse = (s > 0.f) ? (30.f + logf(s)) : -1e30f;
        int cnt = 0;
        float sum = 0.f;
#pragma unroll
        for (int c = 0; c < NCHUNK; c++) {
            int pc = g_pcnt[m * NCHUNK + c];
            cnt += pc;
            int pl = pc < CAPC ? pc : CAPC;
            for (int q = 0; q < pl; q++)
                sum += log1pf(expf(lse - g_posx[(m * NCHUNK + c) * CAPC + q]));
        }
        instS = sum / fmaxf((float)cnt, 1.f);
        if (v3) {
            float s2 = 0.f;
#pragma unroll
            for (int c = 0; c < NCHUNK; c++)
#pragma unroll
                for (int w = 0; w < 8; w++)
                    s2 += g_s_reid[(m * NCHUNK + c) * 8 + w];
            ceS = (30.f + logf(s2)) - g_xt[m];
        }
    }
    float vals[5] = {instS, ceS, v ? 1.f : 0.f, v2 ? 1.f : 0.f, v3 ? 1.f : 0.f};
#pragma unroll
    for (int k = 0; k < 5; k++)
#pragma unroll
        for (int o = 16; o; o >>= 1)
            vals[k] += __shfl_xor_sync(0xffffffffu, vals[k], o);
    if (lane == 0)
        for (int k = 0; k < 5; k++) sred[wid][k] = vals[k];
    __syncthreads();
    if (tid == 0) {
        float tot[5] = {0, 0, 0, 0, 0};
        for (int w = 0; w < 4; w++)
            for (int k = 0; k < 5; k++) tot[k] += sred[w][k];
        for (int k = 0; k < 5; k++) g_part[blockIdx.x][k] = tot[k];
    }
}

// ---------------------------------------------------------------------------
// Finalize stage 2: combine -> scalar
// ---------------------------------------------------------------------------
__global__ void finalize2_kernel(float* __restrict__ out) {
    if (threadIdx.x == 0) {
        float tot[5] = {0, 0, 0, 0, 0};
        for (int b = 0; b < NMTILE; b++)
            for (int k = 0; k < 5; k++) tot[k] += g_part[b][k];
        float fc = 0.f;
        for (int b = 0; b < NMTILE; b++) fc += g_fc[b];
        out[0] = fc / (fmaxf(tot[2], 1.f) * (float)NF)
               + tot[1] / fmaxf(tot[4], 1.f)
               + tot[0] / fmaxf(tot[3], 1.f);
    }
}

// ---------------------------------------------------------------------------
extern "C" void kernel_launch(void* const* d_in, const int* in_sizes, int n_in,
                              void* d_out, int out_size) {
    const float* inputs      = (const float*)d_in[0];
    const int*   roi_label   = (const int*)d_in[1];
    const float* lut_inst    = (const float*)d_in[2];
    const float* reid_lut    = (const float*)d_in[3];
    const int*   reid_labels = (const int*)d_in[4];
    float* out = (float*)d_out;

    cudaFuncSetAttribute(main_kernel, cudaFuncAttributeMaxDynamicSharedMemorySize,
                         SMEM_TOTAL);

    convert_kernel<<<128, 256>>>(inputs, lut_inst, reid_lut);
    fc_kernel<<<NMTILE, 256>>>(inputs, roi_label, lut_inst);
    main_kernel<<<dim3(NMTILE, NCHUNK), 512, SMEM_TOTAL>>>(roi_label, reid_labels);
    finalize1_kernel<<<NMTILE, 128>>>(roi_label, reid_labels);
    finalize2_kernel<<<1, 32>>>(out);
}